// round 2
// baseline (speedup 1.0000x reference)
#include <cuda_runtime.h>
#include <cstdint>

// Screen / tiling constants (W=1280, H=720 are exact multiples of L=16)
#define W_SCREEN 1280
#define H_SCREEN 720
#define NBW      80
#define NBH      45
#define N_POINTS 32768

// Per-point AABB in pixels, packed as ushort4 {xmin, xmax, ymin, ymax}.
__device__ __align__(16) ushort4 g_box[N_POINTS];

// Kernel 1: per-point clamped AABB (exactly mirrors reference create_tiles).
__global__ void prep_kernel(const float* __restrict__ pos2d,
                            const float* __restrict__ radius) {
    int i = blockIdx.x * blockDim.x + threadIdx.x;
    if (i >= N_POINTS) return;
    float x = pos2d[2 * i];
    float y = pos2d[2 * i + 1];
    float r = radius[i];
    int xmin = (int)fminf(fmaxf(x - r, 0.0f), (float)W_SCREEN);
    int xmax = (int)fminf(fmaxf(x + r, 0.0f), (float)W_SCREEN);
    int ymin = (int)fminf(fmaxf(y - r, 0.0f), (float)H_SCREEN);
    int ymax = (int)fminf(fmaxf(y + r, 0.0f), (float)H_SCREEN);
    g_box[i] = make_ushort4((unsigned short)xmin, (unsigned short)xmax,
                            (unsigned short)ymin, (unsigned short)ymax);
}

// Kernel 2: one block column per xi (blockIdx.y), each thread owns 4
// consecutive points and sweeps yi = 0..44, emitting one float4 per row.
//
// Reference condition per (tile, point):
//   min(xmax,right) > max(xmin,left)  &&  min(ymax,bottom) > max(ymin,top)
// With right = left+16 and bottom = top+16 exact (W,H multiples of 16) and
// xmax>xmin, ymax>ymin guaranteed (radius >= 1), this reduces to
//   (xmax > left && xmin < right) && (ymax > top && ymin < bottom).
__global__ __launch_bounds__(128) void mask_kernel(float* __restrict__ out) {
    int g  = blockIdx.x * 128 + threadIdx.x;   // 4-point group, 0..8191
    int xi = blockIdx.y;                       // 0..79
    int left  = xi * 16;
    int right = left + 16;

    // Load 4 points' boxes (32 bytes) as two uint4.
    const uint4* boxes = reinterpret_cast<const uint4*>(g_box);
    uint4 w0 = boxes[2 * g];       // points 4g, 4g+1
    uint4 w1 = boxes[2 * g + 1];   // points 4g+2, 4g+3

    int ylo[4], yhi[4];
    {
        unsigned xw[4] = {w0.x, w0.z, w1.x, w1.z};   // xmin | xmax<<16
        unsigned yw[4] = {w0.y, w0.w, w1.y, w1.w};   // ymin | ymax<<16
#pragma unroll
        for (int j = 0; j < 4; j++) {
            int xmin = (int)(xw[j] & 0xFFFFu);
            int xmax = (int)(xw[j] >> 16);
            int ymin = (int)(yw[j] & 0xFFFFu);
            int ymax = (int)(yw[j] >> 16);
            bool okx = (xmax > left) && (xmin < right);
            ylo[j] = ymin;
            yhi[j] = okx ? ymax : 0;   // poison: y-test can never pass
        }
    }

    float* optr = out + (size_t)xi * NBH * N_POINTS + (size_t)g * 4;

#pragma unroll 5
    for (int yi = 0; yi < NBH; yi++) {
        int top    = yi * 16;
        int bottom = top + 16;
        float4 v;
        v.x = (yhi[0] > top && ylo[0] < bottom) ? 1.0f : 0.0f;
        v.y = (yhi[1] > top && ylo[1] < bottom) ? 1.0f : 0.0f;
        v.z = (yhi[2] > top && ylo[2] < bottom) ? 1.0f : 0.0f;
        v.w = (yhi[3] > top && ylo[3] < bottom) ? 1.0f : 0.0f;
        *reinterpret_cast<float4*>(optr) = v;
        optr += N_POINTS;
    }
}

extern "C" void kernel_launch(void* const* d_in, const int* in_sizes, int n_in,
                              void* d_out, int out_size) {
    const float* pos2d  = (const float*)d_in[0];   // [32768, 2] float32
    const float* radius = (const float*)d_in[1];   // [32768]    float32
    float* out          = (float*)d_out;           // [3600, 32768] float32 (bool promoted)

    prep_kernel<<<128, 256>>>(pos2d, radius);
    dim3 grid(64, NBW);                            // 64 point-chunks x 80 xi
    mask_kernel<<<grid, 128>>>(out);
}